// round 1
// baseline (speedup 1.0000x reference)
#include <cuda_runtime.h>
#include <cuda_bf16.h>
#include <math.h>

// ---------------------------------------------------------------------------
// Problem constants (setup_inputs): N=50000 nodes, E=400000 edges, F=256.
// Layers: 256->8x32, 256->4x32, 128->2x32, 64->1x32 (final: mean over H=1,
// then log_softmax over 32 classes).
// ---------------------------------------------------------------------------
#define MAXN 50000
#define MAXE 400000

// Scratch (static device globals; no allocation anywhere).
__device__ float g_bufA[MAXN * 256];   // h = x @ W  (per layer)
__device__ float g_bufB[MAXN * 256];   // layer output (ping)
__device__ float g_s[MAXN * 8];        // per-(node,head) src score
__device__ float g_d[MAXN * 8];        // per-(node,head) dst score
__device__ int   g_deg[MAXN];
__device__ int   g_rowptr[MAXN + 1];
__device__ int   g_cur[MAXN];
__device__ int   g_col[MAXE];
__device__ int   g_is64;               // edge_index dtype flag

// ---------------------------------------------------------------------------
// edge_index dtype detection: if data is int64 (little-endian, values < 2^31),
// every odd 32-bit word is 0. For int32 data those words are random node ids.
// ---------------------------------------------------------------------------
__global__ void detect_dtype_kernel(const int* __restrict__ ei32, int E) {
    int all_zero = 1;
    for (int i = 1; i < 64 && i < 2 * E; i += 2)
        if (ei32[i] != 0) { all_zero = 0; break; }
    g_is64 = all_zero;
}

__device__ __forceinline__ int edge_val(const void* ei, int E, int which, int e) {
    // which: 0 = src row, 1 = dst row
    if (g_is64) {
        const long long* p = (const long long*)ei;
        return (int)p[(size_t)which * E + e];
    } else {
        const int* p = (const int*)ei;
        return p[(size_t)which * E + e];
    }
}

// ---------------------------------------------------------------------------
// CSR build (by dst)
// ---------------------------------------------------------------------------
__global__ void zero_deg_kernel(int N) {
    int i = blockIdx.x * blockDim.x + threadIdx.x;
    if (i < N) g_deg[i] = 0;
}

__global__ void hist_kernel(const void* __restrict__ ei, int E) {
    int e = blockIdx.x * blockDim.x + threadIdx.x;
    if (e < E) {
        int d = edge_val(ei, E, 1, e);
        atomicAdd(&g_deg[d], 1);
    }
}

// Single-block exclusive scan of g_deg -> g_rowptr (and copy into g_cur).
__global__ void scan_kernel(int N) {
    __shared__ int warp_sums[32];
    __shared__ int carry;
    int tid = threadIdx.x;
    int lane = tid & 31;
    int warp = tid >> 5;
    if (tid == 0) carry = 0;
    __syncthreads();
    for (int base = 0; base < N; base += blockDim.x) {
        int i = base + tid;
        int v = (i < N) ? g_deg[i] : 0;
        // inclusive scan within warp
        int x = v;
        #pragma unroll
        for (int off = 1; off < 32; off <<= 1) {
            int y = __shfl_up_sync(0xFFFFFFFFu, x, off);
            if (lane >= off) x += y;
        }
        if (lane == 31) warp_sums[warp] = x;
        __syncthreads();
        if (tid < 32) {
            int y = warp_sums[tid];
            #pragma unroll
            for (int off = 1; off < 32; off <<= 1) {
                int z = __shfl_up_sync(0xFFFFFFFFu, y, off);
                if (tid >= off) y += z;
            }
            warp_sums[tid] = y;
        }
        __syncthreads();
        int woff = (warp > 0) ? warp_sums[warp - 1] : 0;
        int incl = x + woff + carry;
        if (i < N) {
            g_rowptr[i] = incl - v;
            g_cur[i]    = incl - v;
        }
        __syncthreads();
        if (tid == blockDim.x - 1) carry = incl;
        __syncthreads();
    }
    if (tid == 0) g_rowptr[N] = carry;
}

__global__ void scatter_kernel(const void* __restrict__ ei, int E) {
    int e = blockIdx.x * blockDim.x + threadIdx.x;
    if (e < E) {
        int d = edge_val(ei, E, 1, e);
        int s = edge_val(ei, E, 0, e);
        int p = atomicAdd(&g_cur[d], 1);
        g_col[p] = s;
    }
}

// ---------------------------------------------------------------------------
// Tiled fp32 GEMM: C[M,N] = A[M,K] @ B[K,N].  BM=128, BK=16, TM=8.
// N is a multiple of BN; K is a multiple of BK; M guarded.
// ---------------------------------------------------------------------------
template <int BN, int TN>
__global__ void gemm_kernel(const float* __restrict__ A, const float* __restrict__ B,
                            float* __restrict__ C, int M, int K, int N) {
    constexpr int BM = 128, BK = 16, TM = 8;
    constexpr int TX = BN / TN;           // 16
    __shared__ float As[BK][BM];
    __shared__ float Bs[BK][BN];

    int tid = threadIdx.x;                // 256 threads
    int tx = tid % TX;
    int ty = tid / TX;
    int m0 = blockIdx.x * BM;
    int n0 = blockIdx.y * BN;

    float acc[TM][TN];
    #pragma unroll
    for (int i = 0; i < TM; ++i)
        #pragma unroll
        for (int j = 0; j < TN; ++j) acc[i][j] = 0.f;

    int arow = tid % BM;                  // 0..127
    int akh  = tid / BM;                  // 0..1

    for (int k0 = 0; k0 < K; k0 += BK) {
        // Load A tile (coalesced float4 along K), store transposed As[k][m].
        int gm = m0 + arow;
        #pragma unroll
        for (int q = 0; q < 2; ++q) {
            int kk = akh * 8 + q * 4;
            float4 v = make_float4(0.f, 0.f, 0.f, 0.f);
            if (gm < M)
                v = *reinterpret_cast<const float4*>(&A[(size_t)gm * K + k0 + kk]);
            As[kk + 0][arow] = v.x;
            As[kk + 1][arow] = v.y;
            As[kk + 2][arow] = v.z;
            As[kk + 3][arow] = v.w;
        }
        // Load B tile.
        #pragma unroll
        for (int idx = tid; idx < BK * BN; idx += 256) {
            int kk = idx / BN, cc = idx % BN;
            Bs[kk][cc] = B[(size_t)(k0 + kk) * N + n0 + cc];
        }
        __syncthreads();

        #pragma unroll
        for (int kk = 0; kk < BK; ++kk) {
            float a[TM], b[TN];
            #pragma unroll
            for (int i = 0; i < TM; ++i) a[i] = As[kk][ty * TM + i];
            #pragma unroll
            for (int j = 0; j < TN; ++j) b[j] = Bs[kk][tx * TN + j];
            #pragma unroll
            for (int i = 0; i < TM; ++i)
                #pragma unroll
                for (int j = 0; j < TN; ++j)
                    acc[i][j] = fmaf(a[i], b[j], acc[i][j]);
        }
        __syncthreads();
    }

    #pragma unroll
    for (int i = 0; i < TM; ++i) {
        int gm = m0 + ty * TM + i;
        if (gm >= M) continue;
        #pragma unroll
        for (int j = 0; j < TN; ++j)
            C[(size_t)gm * N + n0 + tx * TN + j] = acc[i][j];
    }
}

// ---------------------------------------------------------------------------
// Per-(node,head) attention scores: s = <h[n,hh,:], a_src[hh,:]>, same for d.
// One warp per (node, head).
// ---------------------------------------------------------------------------
__global__ void sd_kernel(const float* __restrict__ h, const float* __restrict__ a_src,
                          const float* __restrict__ a_dst, float* __restrict__ s,
                          float* __restrict__ d, int N, int H) {
    int wid = blockIdx.x * 8 + (threadIdx.x >> 5);
    int lane = threadIdx.x & 31;
    if (wid >= N * H) return;
    int n = wid / H;
    int hh = wid - n * H;
    int HC = H * 32;
    float hv = h[(size_t)n * HC + hh * 32 + lane];
    float vs = hv * a_src[hh * 32 + lane];
    float vd = hv * a_dst[hh * 32 + lane];
    #pragma unroll
    for (int off = 16; off > 0; off >>= 1) {
        vs += __shfl_down_sync(0xFFFFFFFFu, vs, off);
        vd += __shfl_down_sync(0xFFFFFFFFu, vd, off);
    }
    if (lane == 0) { s[wid] = vs; d[wid] = vd; }
}

// ---------------------------------------------------------------------------
// Aggregation with online softmax. One warp per (node, head).
// Self-loop handled implicitly as the initial state.
// ACT: 0 = bias + ELU, 1 = bias + log_softmax over 32 classes (H==1).
// ---------------------------------------------------------------------------
template <int ACT>
__global__ void agg_kernel(const float* __restrict__ h, const float* __restrict__ s,
                           const float* __restrict__ dts,
                           const float* __restrict__ bias,
                           float* __restrict__ out, int N, int H) {
    int wid = blockIdx.x * 8 + (threadIdx.x >> 5);
    int lane = threadIdx.x & 31;
    if (wid >= N * H) return;
    int n = wid / H;
    int hh = wid - n * H;
    int HC = H * 32;

    float sn = s[wid];
    float dn = dts[wid];
    float e0 = sn + dn;
    e0 = (e0 > 0.f) ? e0 : 0.2f * e0;

    float m = e0;
    float den = 1.f;
    float acc = h[(size_t)n * HC + hh * 32 + lane];

    int r0 = g_rowptr[n];
    int r1 = g_rowptr[n + 1];
    for (int j = r0; j < r1; ++j) {
        int src = g_col[j];
        float e = s[src * H + hh] + dn;
        e = (e > 0.f) ? e : 0.2f * e;
        float mn = fmaxf(m, e);
        float so = __expf(m - mn);
        float w  = __expf(e - mn);
        den = den * so + w;
        acc = acc * so + w * h[(size_t)src * HC + hh * 32 + lane];
        m = mn;
    }

    float o = acc / den + bias[hh * 32 + lane];
    if (ACT == 0) {
        out[(size_t)n * HC + hh * 32 + lane] = (o > 0.f) ? o : expm1f(o);
    } else {
        // H == 1: log_softmax over the 32 classes held by this warp.
        float mx = o;
        #pragma unroll
        for (int off = 16; off > 0; off >>= 1)
            mx = fmaxf(mx, __shfl_xor_sync(0xFFFFFFFFu, mx, off));
        float ex = __expf(o - mx);
        float sum = ex;
        #pragma unroll
        for (int off = 16; off > 0; off >>= 1)
            sum += __shfl_xor_sync(0xFFFFFFFFu, sum, off);
        out[(size_t)n * 32 + lane] = o - mx - logf(sum);
    }
}

// ---------------------------------------------------------------------------
// Launch
// ---------------------------------------------------------------------------
extern "C" void kernel_launch(void* const* d_in, const int* in_sizes, int n_in,
                              void* d_out, int out_size) {
    const float* x  = (const float*)d_in[0];
    const void*  ei = d_in[1];
    const float* W[4]    = {(const float*)d_in[2],  (const float*)d_in[6],
                            (const float*)d_in[10], (const float*)d_in[14]};
    const float* asrc[4] = {(const float*)d_in[3],  (const float*)d_in[7],
                            (const float*)d_in[11], (const float*)d_in[15]};
    const float* adst[4] = {(const float*)d_in[4],  (const float*)d_in[8],
                            (const float*)d_in[12], (const float*)d_in[16]};
    const float* bs[4]   = {(const float*)d_in[5],  (const float*)d_in[9],
                            (const float*)d_in[13], (const float*)d_in[17]};

    int N = in_sizes[0] / 256;     // x is [N, 256]
    int E = in_sizes[1] / 2;       // edge_index is [2, E]

    float *bufA, *bufB, *sb, *db;
    cudaGetSymbolAddress((void**)&bufA, g_bufA);
    cudaGetSymbolAddress((void**)&bufB, g_bufB);
    cudaGetSymbolAddress((void**)&sb,   g_s);
    cudaGetSymbolAddress((void**)&db,   g_d);

    // --- CSR build (by dst) ---
    detect_dtype_kernel<<<1, 1>>>((const int*)ei, E);
    zero_deg_kernel<<<(N + 255) / 256, 256>>>(N);
    hist_kernel<<<(E + 255) / 256, 256>>>(ei, E);
    scan_kernel<<<1, 1024>>>(N);
    scatter_kernel<<<(E + 255) / 256, 256>>>(ei, E);

    // --- 4 GAT layers ---
    const int Hs[4]  = {8, 4, 2, 1};
    const int Ks[4]  = {256, 256, 128, 64};
    const int HCs[4] = {256, 128, 64, 32};

    const float* in = x;
    for (int L = 0; L < 4; ++L) {
        int K = Ks[L], HC = HCs[L], H = Hs[L];
        if (L < 3) {
            dim3 g((N + 127) / 128, HC / 64);
            gemm_kernel<64, 4><<<g, 256>>>(in, W[L], bufA, N, K, HC);
        } else {
            dim3 g((N + 127) / 128, 1);
            gemm_kernel<32, 2><<<g, 256>>>(in, W[L], bufA, N, K, HC);
        }
        int warps = N * H;
        int blocks = (warps + 7) / 8;
        sd_kernel<<<blocks, 256>>>(bufA, asrc[L], adst[L], sb, db, N, H);
        if (L < 3) {
            agg_kernel<0><<<blocks, 256>>>(bufA, sb, db, bs[L], bufB, N, H);
            in = bufB;
        } else {
            agg_kernel<1><<<blocks, 256>>>(bufA, sb, db, bs[L], (float*)d_out, N, H);
        }
    }
}

// round 2
// speedup vs baseline: 1.3784x; 1.3784x over previous
#include <cuda_runtime.h>
#include <cuda_bf16.h>
#include <math.h>
#include <stdint.h>

// ---------------------------------------------------------------------------
// GAT, 4 layers. N=50000, E=400000, F=256.
// Layers: 256->8x32, 256->4x32, 128->2x32, 64->1x32 (+ final log_softmax).
// ---------------------------------------------------------------------------
#define MAXN 50000
#define MAXE 400000

__device__ float g_bufA[MAXN * 256];   // h = x @ W (per layer)
__device__ float g_bufB[MAXN * 256];   // layer output (ping)
__device__ float g_s[MAXN * 8];
__device__ float g_d[MAXN * 8];
__device__ int   g_deg[MAXN];
__device__ int   g_rowptr[MAXN + 1];
__device__ int   g_cur[MAXN];
__device__ int   g_col[MAXE];
__device__ int   g_bsum[1024];
__device__ int   g_boff[1024];
__device__ int   g_is64;

// ---------------------------------------------------------------------------
// edge_index dtype detection (int64 vs int32)
// ---------------------------------------------------------------------------
__global__ void detect_dtype_kernel(const int* __restrict__ ei32, int E) {
    int all_zero = 1;
    for (int i = 1; i < 64 && i < 2 * E; i += 2)
        if (ei32[i] != 0) { all_zero = 0; break; }
    g_is64 = all_zero;
}

__device__ __forceinline__ int edge_val(const void* ei, int E, int which, int e) {
    if (g_is64) {
        const long long* p = (const long long*)ei;
        return (int)p[(size_t)which * E + e];
    } else {
        const int* p = (const int*)ei;
        return p[(size_t)which * E + e];
    }
}

// ---------------------------------------------------------------------------
// CSR build (by dst)
// ---------------------------------------------------------------------------
__global__ void zero_deg_kernel(int N) {
    int i = blockIdx.x * blockDim.x + threadIdx.x;
    if (i < N) g_deg[i] = 0;
}

__global__ void hist_kernel(const void* __restrict__ ei, int E) {
    int e = blockIdx.x * blockDim.x + threadIdx.x;
    if (e < E) atomicAdd(&g_deg[edge_val(ei, E, 1, e)], 1);
}

// Two-level scan: scan1 (per-block excl scan + block sums), scan2 (scan the
// block sums, one block), scan3 (add block offsets).
__global__ void scan1_kernel(int N) {
    __shared__ int ws[16];
    int tid = threadIdx.x;                 // 512 threads
    int lane = tid & 31, warp = tid >> 5;
    int i = blockIdx.x * 512 + tid;
    int v = (i < N) ? g_deg[i] : 0;
    int x = v;
    #pragma unroll
    for (int off = 1; off < 32; off <<= 1) {
        int y = __shfl_up_sync(0xFFFFFFFFu, x, off);
        if (lane >= off) x += y;
    }
    if (lane == 31) ws[warp] = x;
    __syncthreads();
    if (tid < 16) {
        int y = ws[tid];
        #pragma unroll
        for (int off = 1; off < 16; off <<= 1) {
            int z = __shfl_up_sync(0x0000FFFFu, y, off);
            if (tid >= off) y += z;
        }
        ws[tid] = y;
    }
    __syncthreads();
    int woff = (warp > 0) ? ws[warp - 1] : 0;
    if (i < N) g_rowptr[i] = x - v + woff;   // block-local exclusive
    if (tid == 0) g_bsum[blockIdx.x] = ws[15];
}

__global__ void scan2_kernel(int nb, int N) {
    __shared__ int ws[4];
    int tid = threadIdx.x;                 // 128 threads, nb <= 128
    int lane = tid & 31, warp = tid >> 5;
    int v = (tid < nb) ? g_bsum[tid] : 0;
    int x = v;
    #pragma unroll
    for (int off = 1; off < 32; off <<= 1) {
        int y = __shfl_up_sync(0xFFFFFFFFu, x, off);
        if (lane >= off) x += y;
    }
    if (lane == 31) ws[warp] = x;
    __syncthreads();
    if (tid < 4) {
        int y = ws[tid];
        #pragma unroll
        for (int off = 1; off < 4; off <<= 1) {
            int z = __shfl_up_sync(0x0000000Fu, y, off);
            if (tid >= off) y += z;
        }
        ws[tid] = y;
    }
    __syncthreads();
    int woff = (warp > 0) ? ws[warp - 1] : 0;
    g_boff[tid] = x - v + woff;
    if (tid == 127) g_rowptr[N] = x + woff;  // grand total
}

__global__ void scan3_kernel(int N) {
    int i = blockIdx.x * 512 + threadIdx.x;
    if (i < N) {
        int val = g_rowptr[i] + g_boff[blockIdx.x];
        g_rowptr[i] = val;
        g_cur[i] = val;
    }
}

__global__ void scatter_kernel(const void* __restrict__ ei, int E) {
    int e = blockIdx.x * blockDim.x + threadIdx.x;
    if (e < E) {
        int d = edge_val(ei, E, 1, e);
        int s = edge_val(ei, E, 0, e);
        g_col[atomicAdd(&g_cur[d], 1)] = s;
    }
}

// ---------------------------------------------------------------------------
// Tensor-core GEMM: C[M,N] = A[M,K] @ B[K,N], fp32 in/out.
// bf16 2-term split: A ~= Ah + Al, B ~= Bh + Bl; C = AhBh + AlBh + AhBl.
// BM=128, BK=32, 8 warps/block. BN=64 (warps 4x2, warp tile 32x32) or
// BN=32 (warps 8x1, warp tile 16x32).
// ---------------------------------------------------------------------------
__device__ __forceinline__ void ldsm_x4(uint32_t& r0, uint32_t& r1, uint32_t& r2,
                                        uint32_t& r3, uint32_t addr) {
    asm volatile("ldmatrix.sync.aligned.m8n8.x4.shared.b16 {%0,%1,%2,%3}, [%4];\n"
                 : "=r"(r0), "=r"(r1), "=r"(r2), "=r"(r3) : "r"(addr));
}
__device__ __forceinline__ void ldsm_x4_t(uint32_t& r0, uint32_t& r1, uint32_t& r2,
                                          uint32_t& r3, uint32_t addr) {
    asm volatile("ldmatrix.sync.aligned.m8n8.x4.trans.shared.b16 {%0,%1,%2,%3}, [%4];\n"
                 : "=r"(r0), "=r"(r1), "=r"(r2), "=r"(r3) : "r"(addr));
}
__device__ __forceinline__ void mma_bf16(float* c, const uint32_t* a,
                                         uint32_t b0, uint32_t b1) {
    asm volatile(
        "mma.sync.aligned.m16n8k16.row.col.f32.bf16.bf16.f32 "
        "{%0,%1,%2,%3}, {%4,%5,%6,%7}, {%8,%9}, {%0,%1,%2,%3};\n"
        : "+f"(c[0]), "+f"(c[1]), "+f"(c[2]), "+f"(c[3])
        : "r"(a[0]), "r"(a[1]), "r"(a[2]), "r"(a[3]), "r"(b0), "r"(b1));
}

__device__ __forceinline__ void cvt_store4(__nv_bfloat16* ph, __nv_bfloat16* pl,
                                           float4 f) {
    __nv_bfloat16 h0 = __float2bfloat16(f.x);
    __nv_bfloat16 h1 = __float2bfloat16(f.y);
    __nv_bfloat16 h2 = __float2bfloat16(f.z);
    __nv_bfloat16 h3 = __float2bfloat16(f.w);
    __nv_bfloat16 l0 = __float2bfloat16(f.x - __bfloat162float(h0));
    __nv_bfloat16 l1 = __float2bfloat16(f.y - __bfloat162float(h1));
    __nv_bfloat16 l2 = __float2bfloat16(f.z - __bfloat162float(h2));
    __nv_bfloat16 l3 = __float2bfloat16(f.w - __bfloat162float(h3));
    reinterpret_cast<__nv_bfloat162*>(ph)[0] = __nv_bfloat162(h0, h1);
    reinterpret_cast<__nv_bfloat162*>(ph)[1] = __nv_bfloat162(h2, h3);
    reinterpret_cast<__nv_bfloat162*>(pl)[0] = __nv_bfloat162(l0, l1);
    reinterpret_cast<__nv_bfloat162*>(pl)[1] = __nv_bfloat162(l2, l3);
}

template <int BN, int WARPS_M, int WARPS_N, int WM>
__global__ __launch_bounds__(256, 2)
void gemm_mma_kernel(const float* __restrict__ A, const float* __restrict__ B,
                     float* __restrict__ C, int M, int K, int N) {
    constexpr int BM = 128, BK = 32;
    constexpr int AP = 40;        // padded A row (bf16 elems) -> 80B stride
    constexpr int BP = BN + 8;    // padded B row
    __shared__ __align__(16) __nv_bfloat16 Ah[BM][AP];
    __shared__ __align__(16) __nv_bfloat16 Al[BM][AP];
    __shared__ __align__(16) __nv_bfloat16 Bh[BK][BP];
    __shared__ __align__(16) __nv_bfloat16 Bl[BK][BP];

    int tid = threadIdx.x, lane = tid & 31, warp = tid >> 5;
    int wm = warp % WARPS_M, wn = warp / WARPS_M;
    int wrow = wm * (WM * 16);
    int wcol = wn * 32;
    int m0 = blockIdx.x * BM, n0 = blockIdx.y * BN;

    float c[WM][4][4];
    #pragma unroll
    for (int i = 0; i < WM; ++i)
        #pragma unroll
        for (int j = 0; j < 4; ++j)
            #pragma unroll
            for (int q = 0; q < 4; ++q) c[i][j][q] = 0.f;

    for (int k0 = 0; k0 < K; k0 += BK) {
        // Load + convert A tile: 128x32 floats = 1024 float4, 256 threads x 4
        #pragma unroll
        for (int it = 0; it < 4; ++it) {
            int v = tid + it * 256;
            int row = v >> 3, kq = v & 7;
            int gm = m0 + row;
            float4 f = make_float4(0.f, 0.f, 0.f, 0.f);
            if (gm < M)
                f = *reinterpret_cast<const float4*>(&A[(size_t)gm * K + k0 + kq * 4]);
            cvt_store4(&Ah[row][kq * 4], &Al[row][kq * 4], f);
        }
        // Load + convert B tile: 32xBN floats
        constexpr int BV = (BK * BN / 4) / 256;  // 2 (BN=64) or 1 (BN=32)
        #pragma unroll
        for (int it = 0; it < BV; ++it) {
            int v = tid + it * 256;
            int row = v / (BN / 4), cq = v % (BN / 4);
            float4 f = *reinterpret_cast<const float4*>(
                &B[(size_t)(k0 + row) * N + n0 + cq * 4]);
            cvt_store4(&Bh[row][cq * 4], &Bl[row][cq * 4], f);
        }
        __syncthreads();

        #pragma unroll
        for (int kk = 0; kk < BK; kk += 16) {
            uint32_t ah[WM][4], al[WM][4], bh[2][4], bl[2][4];
            #pragma unroll
            for (int im = 0; im < WM; ++im) {
                uint32_t addr_h = (uint32_t)__cvta_generic_to_shared(
                    &Ah[wrow + im * 16 + (lane & 15)][kk + (lane >> 4) * 8]);
                ldsm_x4(ah[im][0], ah[im][1], ah[im][2], ah[im][3], addr_h);
                uint32_t addr_l = (uint32_t)__cvta_generic_to_shared(
                    &Al[wrow + im * 16 + (lane & 15)][kk + (lane >> 4) * 8]);
                ldsm_x4(al[im][0], al[im][1], al[im][2], al[im][3], addr_l);
            }
            #pragma unroll
            for (int jn = 0; jn < 2; ++jn) {
                uint32_t addr_h = (uint32_t)__cvta_generic_to_shared(
                    &Bh[kk + (lane & 15)][wcol + jn * 16 + (lane >> 4) * 8]);
                ldsm_x4_t(bh[jn][0], bh[jn][1], bh[jn][2], bh[jn][3], addr_h);
                uint32_t addr_l = (uint32_t)__cvta_generic_to_shared(
                    &Bl[kk + (lane & 15)][wcol + jn * 16 + (lane >> 4) * 8]);
                ldsm_x4_t(bl[jn][0], bl[jn][1], bl[jn][2], bl[jn][3], addr_l);
            }
            #pragma unroll
            for (int im = 0; im < WM; ++im) {
                #pragma unroll
                for (int j = 0; j < 4; ++j) {
                    uint32_t b0h = bh[j >> 1][(j & 1) * 2];
                    uint32_t b1h = bh[j >> 1][(j & 1) * 2 + 1];
                    uint32_t b0l = bl[j >> 1][(j & 1) * 2];
                    uint32_t b1l = bl[j >> 1][(j & 1) * 2 + 1];
                    mma_bf16(c[im][j], ah[im], b0h, b1h);
                    mma_bf16(c[im][j], al[im], b0h, b1h);
                    mma_bf16(c[im][j], ah[im], b0l, b1l);
                }
            }
        }
        __syncthreads();
    }

    // Epilogue
    #pragma unroll
    for (int im = 0; im < WM; ++im) {
        #pragma unroll
        for (int j = 0; j < 4; ++j) {
            int r = wrow + im * 16 + (lane >> 2);
            int col = n0 + wcol + j * 8 + (lane & 3) * 2;
            int gm = m0 + r;
            if (gm < M) {
                C[(size_t)gm * N + col]     = c[im][j][0];
                C[(size_t)gm * N + col + 1] = c[im][j][1];
            }
            if (gm + 8 < M) {
                C[(size_t)(gm + 8) * N + col]     = c[im][j][2];
                C[(size_t)(gm + 8) * N + col + 1] = c[im][j][3];
            }
        }
    }
}

// ---------------------------------------------------------------------------
// Per-(node,head) attention scores.
// ---------------------------------------------------------------------------
__global__ void sd_kernel(const float* __restrict__ h, const float* __restrict__ a_src,
                          const float* __restrict__ a_dst, float* __restrict__ s,
                          float* __restrict__ d, int N, int H) {
    int wid = blockIdx.x * 8 + (threadIdx.x >> 5);
    int lane = threadIdx.x & 31;
    if (wid >= N * H) return;
    int n = wid / H;
    int hh = wid - n * H;
    int HC = H * 32;
    float hv = h[(size_t)n * HC + hh * 32 + lane];
    float vs = hv * a_src[hh * 32 + lane];
    float vd = hv * a_dst[hh * 32 + lane];
    #pragma unroll
    for (int off = 16; off > 0; off >>= 1) {
        vs += __shfl_down_sync(0xFFFFFFFFu, vs, off);
        vd += __shfl_down_sync(0xFFFFFFFFu, vd, off);
    }
    if (lane == 0) { s[wid] = vs; d[wid] = vd; }
}

// ---------------------------------------------------------------------------
// Aggregation with online softmax. One warp per (node, head).
// ---------------------------------------------------------------------------
template <int ACT>
__global__ void agg_kernel(const float* __restrict__ h, const float* __restrict__ s,
                           const float* __restrict__ dts,
                           const float* __restrict__ bias,
                           float* __restrict__ out, int N, int H) {
    int wid = blockIdx.x * 8 + (threadIdx.x >> 5);
    int lane = threadIdx.x & 31;
    if (wid >= N * H) return;
    int n = wid / H;
    int hh = wid - n * H;
    int HC = H * 32;

    float sn = s[wid];
    float dn = dts[wid];
    float e0 = sn + dn;
    e0 = (e0 > 0.f) ? e0 : 0.2f * e0;

    float m = e0;
    float den = 1.f;
    float acc = h[(size_t)n * HC + hh * 32 + lane];

    int r0 = g_rowptr[n];
    int r1 = g_rowptr[n + 1];
    for (int j = r0; j < r1; ++j) {
        int src = g_col[j];
        float e = s[src * H + hh] + dn;
        e = (e > 0.f) ? e : 0.2f * e;
        float mn = fmaxf(m, e);
        float so = __expf(m - mn);
        float w  = __expf(e - mn);
        den = den * so + w;
        acc = acc * so + w * h[(size_t)src * HC + hh * 32 + lane];
        m = mn;
    }

    float o = acc / den + bias[hh * 32 + lane];
    if (ACT == 0) {
        out[(size_t)n * HC + hh * 32 + lane] = (o > 0.f) ? o : expm1f(o);
    } else {
        float mx = o;
        #pragma unroll
        for (int off = 16; off > 0; off >>= 1)
            mx = fmaxf(mx, __shfl_xor_sync(0xFFFFFFFFu, mx, off));
        float ex = __expf(o - mx);
        float sum = ex;
        #pragma unroll
        for (int off = 16; off > 0; off >>= 1)
            sum += __shfl_xor_sync(0xFFFFFFFFu, sum, off);
        out[(size_t)n * 32 + lane] = o - mx - logf(sum);
    }
}

// ---------------------------------------------------------------------------
// Launch
// ---------------------------------------------------------------------------
extern "C" void kernel_launch(void* const* d_in, const int* in_sizes, int n_in,
                              void* d_out, int out_size) {
    const float* x  = (const float*)d_in[0];
    const void*  ei = d_in[1];
    const float* W[4]    = {(const float*)d_in[2],  (const float*)d_in[6],
                            (const float*)d_in[10], (const float*)d_in[14]};
    const float* asrc[4] = {(const float*)d_in[3],  (const float*)d_in[7],
                            (const float*)d_in[11], (const float*)d_in[15]};
    const float* adst[4] = {(const float*)d_in[4],  (const float*)d_in[8],
                            (const float*)d_in[12], (const float*)d_in[16]};
    const float* bs[4]   = {(const float*)d_in[5],  (const float*)d_in[9],
                            (const float*)d_in[13], (const float*)d_in[17]};

    int N = in_sizes[0] / 256;
    int E = in_sizes[1] / 2;

    float *bufA, *bufB, *sb, *db;
    cudaGetSymbolAddress((void**)&bufA, g_bufA);
    cudaGetSymbolAddress((void**)&bufB, g_bufB);
    cudaGetSymbolAddress((void**)&sb,   g_s);
    cudaGetSymbolAddress((void**)&db,   g_d);

    // --- CSR build ---
    int nb = (N + 511) / 512;
    detect_dtype_kernel<<<1, 1>>>((const int*)ei, E);
    zero_deg_kernel<<<(N + 255) / 256, 256>>>(N);
    hist_kernel<<<(E + 255) / 256, 256>>>(ei, E);
    scan1_kernel<<<nb, 512>>>(N);
    scan2_kernel<<<1, 128>>>(nb, N);
    scan3_kernel<<<nb, 512>>>(N);
    scatter_kernel<<<(E + 255) / 256, 256>>>(ei, E);

    // --- 4 GAT layers ---
    const int Hs[4]  = {8, 4, 2, 1};
    const int Ks[4]  = {256, 256, 128, 64};
    const int HCs[4] = {256, 128, 64, 32};

    const float* in = x;
    for (int L = 0; L < 4; ++L) {
        int K = Ks[L], HC = HCs[L], H = Hs[L];
        if (L < 3) {
            dim3 g((N + 127) / 128, HC / 64);
            gemm_mma_kernel<64, 4, 2, 2><<<g, 256>>>(in, W[L], bufA, N, K, HC);
        } else {
            dim3 g((N + 127) / 128, 1);
            gemm_mma_kernel<32, 8, 1, 1><<<g, 256>>>(in, W[L], bufA, N, K, HC);
        }
        int warps = N * H;
        int blocks = (warps + 7) / 8;
        sd_kernel<<<blocks, 256>>>(bufA, asrc[L], adst[L], sb, db, N, H);
        if (L < 3) {
            agg_kernel<0><<<blocks, 256>>>(bufA, sb, db, bs[L], bufB, N, H);
            in = bufB;
        } else {
            agg_kernel<1><<<blocks, 256>>>(bufA, sb, db, bs[L], (float*)d_out, N, H);
        }
    }
}

// round 3
// speedup vs baseline: 1.3838x; 1.0039x over previous
#include <cuda_runtime.h>
#include <cuda_bf16.h>
#include <math.h>
#include <stdint.h>

// ---------------------------------------------------------------------------
// GAT, 4 layers. N=50000, E=400000, F=256.
// Layers: 256->8x32, 256->4x32, 128->2x32, 64->1x32 (+ final log_softmax).
// ---------------------------------------------------------------------------
#define MAXN 50000
#define MAXE 400000

__device__ float g_bufA[MAXN * 256];   // h = x @ W (per layer)
__device__ float g_bufB[MAXN * 256];   // layer output (ping)
__device__ float g_s[MAXN * 8];
__device__ float g_d[MAXN * 8];
__device__ int   g_deg[MAXN];
__device__ int   g_rowptr[MAXN + 1];
__device__ int   g_cur[MAXN];
__device__ int   g_col[MAXE];
__device__ int   g_bsum[1024];
__device__ int   g_boff[1024];
__device__ int   g_is64;

// ---------------------------------------------------------------------------
// edge_index dtype detection (int64 vs int32)
// ---------------------------------------------------------------------------
__global__ void detect_dtype_kernel(const int* __restrict__ ei32, int E) {
    int all_zero = 1;
    for (int i = 1; i < 64 && i < 2 * E; i += 2)
        if (ei32[i] != 0) { all_zero = 0; break; }
    g_is64 = all_zero;
}

__device__ __forceinline__ int edge_val(const void* ei, int E, int which, int e) {
    if (g_is64) {
        const long long* p = (const long long*)ei;
        return (int)p[(size_t)which * E + e];
    } else {
        const int* p = (const int*)ei;
        return p[(size_t)which * E + e];
    }
}

// ---------------------------------------------------------------------------
// CSR build (by dst)
// ---------------------------------------------------------------------------
__global__ void zero_deg_kernel(int N) {
    int i = blockIdx.x * blockDim.x + threadIdx.x;
    if (i < N) g_deg[i] = 0;
}

__global__ void hist_kernel(const void* __restrict__ ei, int E) {
    int e = blockIdx.x * blockDim.x + threadIdx.x;
    if (e < E) atomicAdd(&g_deg[edge_val(ei, E, 1, e)], 1);
}

// Two-level scan: scan1 (per-block excl scan + block sums), scan2 (scan the
// block sums, one block), scan3 (add block offsets).
__global__ void scan1_kernel(int N) {
    __shared__ int ws[16];
    int tid = threadIdx.x;                 // 512 threads
    int lane = tid & 31, warp = tid >> 5;
    int i = blockIdx.x * 512 + tid;
    int v = (i < N) ? g_deg[i] : 0;
    int x = v;
    #pragma unroll
    for (int off = 1; off < 32; off <<= 1) {
        int y = __shfl_up_sync(0xFFFFFFFFu, x, off);
        if (lane >= off) x += y;
    }
    if (lane == 31) ws[warp] = x;
    __syncthreads();
    if (tid < 16) {
        int y = ws[tid];
        #pragma unroll
        for (int off = 1; off < 16; off <<= 1) {
            int z = __shfl_up_sync(0x0000FFFFu, y, off);
            if (tid >= off) y += z;
        }
        ws[tid] = y;
    }
    __syncthreads();
    int woff = (warp > 0) ? ws[warp - 1] : 0;
    if (i < N) g_rowptr[i] = x - v + woff;   // block-local exclusive
    if (tid == 0) g_bsum[blockIdx.x] = ws[15];
}

__global__ void scan2_kernel(int nb, int N) {
    __shared__ int ws[4];
    int tid = threadIdx.x;                 // 128 threads, nb <= 128
    int lane = tid & 31, warp = tid >> 5;
    int v = (tid < nb) ? g_bsum[tid] : 0;
    int x = v;
    #pragma unroll
    for (int off = 1; off < 32; off <<= 1) {
        int y = __shfl_up_sync(0xFFFFFFFFu, x, off);
        if (lane >= off) x += y;
    }
    if (lane == 31) ws[warp] = x;
    __syncthreads();
    if (tid < 4) {
        int y = ws[tid];
        #pragma unroll
        for (int off = 1; off < 4; off <<= 1) {
            int z = __shfl_up_sync(0x0000000Fu, y, off);
            if (tid >= off) y += z;
        }
        ws[tid] = y;
    }
    __syncthreads();
    int woff = (warp > 0) ? ws[warp - 1] : 0;
    g_boff[tid] = x - v + woff;
    if (tid == 127) g_rowptr[N] = x + woff;  // grand total
}

__global__ void scan3_kernel(int N) {
    int i = blockIdx.x * 512 + threadIdx.x;
    if (i < N) {
        int val = g_rowptr[i] + g_boff[blockIdx.x];
        g_rowptr[i] = val;
        g_cur[i] = val;
    }
}

__global__ void scatter_kernel(const void* __restrict__ ei, int E) {
    int e = blockIdx.x * blockDim.x + threadIdx.x;
    if (e < E) {
        int d = edge_val(ei, E, 1, e);
        int s = edge_val(ei, E, 0, e);
        g_col[atomicAdd(&g_cur[d], 1)] = s;
    }
}

// ---------------------------------------------------------------------------
// Tensor-core GEMM: C[M,N] = A[M,K] @ B[K,N], fp32 in/out.
// bf16 2-term split: A ~= Ah + Al, B ~= Bh + Bl; C = AhBh + AlBh + AhBl.
// BM=128, BK=32, 8 warps/block. BN=64 (warps 4x2, warp tile 32x32) or
// BN=32 (warps 8x1, warp tile 16x32).
// ---------------------------------------------------------------------------
__device__ __forceinline__ void ldsm_x4(uint32_t& r0, uint32_t& r1, uint32_t& r2,
                                        uint32_t& r3, uint32_t addr) {
    asm volatile("ldmatrix.sync.aligned.m8n8.x4.shared.b16 {%0,%1,%2,%3}, [%4];\n"
                 : "=r"(r0), "=r"(r1), "=r"(r2), "=r"(r3) : "r"(addr));
}
__device__ __forceinline__ void ldsm_x4_t(uint32_t& r0, uint32_t& r1, uint32_t& r2,
                                          uint32_t& r3, uint32_t addr) {
    asm volatile("ldmatrix.sync.aligned.m8n8.x4.trans.shared.b16 {%0,%1,%2,%3}, [%4];\n"
                 : "=r"(r0), "=r"(r1), "=r"(r2), "=r"(r3) : "r"(addr));
}
__device__ __forceinline__ void mma_bf16(float* c, const uint32_t* a,
                                         uint32_t b0, uint32_t b1) {
    asm volatile(
        "mma.sync.aligned.m16n8k16.row.col.f32.bf16.bf16.f32 "
        "{%0,%1,%2,%3}, {%4,%5,%6,%7}, {%8,%9}, {%0,%1,%2,%3};\n"
        : "+f"(c[0]), "+f"(c[1]), "+f"(c[2]), "+f"(c[3])
        : "r"(a[0]), "r"(a[1]), "r"(a[2]), "r"(a[3]), "r"(b0), "r"(b1));
}

__device__ __forceinline__ void cvt_store4(__nv_bfloat16* ph, __nv_bfloat16* pl,
                                           float4 f) {
    __nv_bfloat16 h0 = __float2bfloat16(f.x);
    __nv_bfloat16 h1 = __float2bfloat16(f.y);
    __nv_bfloat16 h2 = __float2bfloat16(f.z);
    __nv_bfloat16 h3 = __float2bfloat16(f.w);
    __nv_bfloat16 l0 = __float2bfloat16(f.x - __bfloat162float(h0));
    __nv_bfloat16 l1 = __float2bfloat16(f.y - __bfloat162float(h1));
    __nv_bfloat16 l2 = __float2bfloat16(f.z - __bfloat162float(h2));
    __nv_bfloat16 l3 = __float2bfloat16(f.w - __bfloat162float(h3));
    reinterpret_cast<__nv_bfloat162*>(ph)[0] = __nv_bfloat162(h0, h1);
    reinterpret_cast<__nv_bfloat162*>(ph)[1] = __nv_bfloat162(h2, h3);
    reinterpret_cast<__nv_bfloat162*>(pl)[0] = __nv_bfloat162(l0, l1);
    reinterpret_cast<__nv_bfloat162*>(pl)[1] = __nv_bfloat162(l2, l3);
}

template <int BN, int WARPS_M, int WARPS_N, int WM>
__global__ __launch_bounds__(256, 2)
void gemm_mma_kernel(const float* __restrict__ A, const float* __restrict__ B,
                     float* __restrict__ C, int M, int K, int N) {
    constexpr int BM = 128, BK = 32;
    constexpr int AP = 40;        // padded A row (bf16 elems) -> 80B stride
    constexpr int BP = BN + 8;    // padded B row
    __shared__ __align__(16) __nv_bfloat16 Ah[BM][AP];
    __shared__ __align__(16) __nv_bfloat16 Al[BM][AP];
    __shared__ __align__(16) __nv_bfloat16 Bh[BK][BP];
    __shared__ __align__(16) __nv_bfloat16 Bl[BK][BP];

    int tid = threadIdx.x, lane = tid & 31, warp = tid >> 5;
    int wm = warp % WARPS_M, wn = warp / WARPS_M;
    int wrow = wm * (WM * 16);
    int wcol = wn * 32;
    int m0 = blockIdx.x * BM, n0 = blockIdx.y * BN;

    float c[WM][4][4];
    #pragma unroll
    for (int i = 0; i < WM; ++i)
        #pragma unroll
        for (int j = 0; j < 4; ++j)
            #pragma unroll
            for (int q = 0; q < 4; ++q) c[i][j][q] = 0.f;

    for (int k0 = 0; k0 < K; k0 += BK) {
        // Load + convert A tile: 128x32 floats = 1024 float4, 256 threads x 4
        #pragma unroll
        for (int it = 0; it < 4; ++it) {
            int v = tid + it * 256;
            int row = v >> 3, kq = v & 7;
            int gm = m0 + row;
            float4 f = make_float4(0.f, 0.f, 0.f, 0.f);
            if (gm < M)
                f = *reinterpret_cast<const float4*>(&A[(size_t)gm * K + k0 + kq * 4]);
            cvt_store4(&Ah[row][kq * 4], &Al[row][kq * 4], f);
        }
        // Load + convert B tile: 32xBN floats
        constexpr int BV = (BK * BN / 4) / 256;  // 2 (BN=64) or 1 (BN=32)
        #pragma unroll
        for (int it = 0; it < BV; ++it) {
            int v = tid + it * 256;
            int row = v / (BN / 4), cq = v % (BN / 4);
            float4 f = *reinterpret_cast<const float4*>(
                &B[(size_t)(k0 + row) * N + n0 + cq * 4]);
            cvt_store4(&Bh[row][cq * 4], &Bl[row][cq * 4], f);
        }
        __syncthreads();

        #pragma unroll
        for (int kk = 0; kk < BK; kk += 16) {
            uint32_t ah[WM][4], al[WM][4], bh[2][4], bl[2][4];
            #pragma unroll
            for (int im = 0; im < WM; ++im) {
                uint32_t addr_h = (uint32_t)__cvta_generic_to_shared(
                    &Ah[wrow + im * 16 + (lane & 15)][kk + (lane >> 4) * 8]);
                ldsm_x4(ah[im][0], ah[im][1], ah[im][2], ah[im][3], addr_h);
                uint32_t addr_l = (uint32_t)__cvta_generic_to_shared(
                    &Al[wrow + im * 16 + (lane & 15)][kk + (lane >> 4) * 8]);
                ldsm_x4(al[im][0], al[im][1], al[im][2], al[im][3], addr_l);
            }
            #pragma unroll
            for (int jn = 0; jn < 2; ++jn) {
                uint32_t addr_h = (uint32_t)__cvta_generic_to_shared(
                    &Bh[kk + (lane & 15)][wcol + jn * 16 + (lane >> 4) * 8]);
                ldsm_x4_t(bh[jn][0], bh[jn][1], bh[jn][2], bh[jn][3], addr_h);
                uint32_t addr_l = (uint32_t)__cvta_generic_to_shared(
                    &Bl[kk + (lane & 15)][wcol + jn * 16 + (lane >> 4) * 8]);
                ldsm_x4_t(bl[jn][0], bl[jn][1], bl[jn][2], bl[jn][3], addr_l);
            }
            #pragma unroll
            for (int im = 0; im < WM; ++im) {
                #pragma unroll
                for (int j = 0; j < 4; ++j) {
                    uint32_t b0h = bh[j >> 1][(j & 1) * 2];
                    uint32_t b1h = bh[j >> 1][(j & 1) * 2 + 1];
                    uint32_t b0l = bl[j >> 1][(j & 1) * 2];
                    uint32_t b1l = bl[j >> 1][(j & 1) * 2 + 1];
                    mma_bf16(c[im][j], ah[im], b0h, b1h);
                    mma_bf16(c[im][j], al[im], b0h, b1h);
                    mma_bf16(c[im][j], ah[im], b0l, b1l);
                }
            }
        }
        __syncthreads();
    }

    // Epilogue
    #pragma unroll
    for (int im = 0; im < WM; ++im) {
        #pragma unroll
        for (int j = 0; j < 4; ++j) {
            int r = wrow + im * 16 + (lane >> 2);
            int col = n0 + wcol + j * 8 + (lane & 3) * 2;
            int gm = m0 + r;
            if (gm < M) {
                C[(size_t)gm * N + col]     = c[im][j][0];
                C[(size_t)gm * N + col + 1] = c[im][j][1];
            }
            if (gm + 8 < M) {
                C[(size_t)(gm + 8) * N + col]     = c[im][j][2];
                C[(size_t)(gm + 8) * N + col + 1] = c[im][j][3];
            }
        }
    }
}

// ---------------------------------------------------------------------------
// Per-(node,head) attention scores.
// ---------------------------------------------------------------------------
__global__ void sd_kernel(const float* __restrict__ h, const float* __restrict__ a_src,
                          const float* __restrict__ a_dst, float* __restrict__ s,
                          float* __restrict__ d, int N, int H) {
    int wid = blockIdx.x * 8 + (threadIdx.x >> 5);
    int lane = threadIdx.x & 31;
    if (wid >= N * H) return;
    int n = wid / H;
    int hh = wid - n * H;
    int HC = H * 32;
    float hv = h[(size_t)n * HC + hh * 32 + lane];
    float vs = hv * a_src[hh * 32 + lane];
    float vd = hv * a_dst[hh * 32 + lane];
    #pragma unroll
    for (int off = 16; off > 0; off >>= 1) {
        vs += __shfl_down_sync(0xFFFFFFFFu, vs, off);
        vd += __shfl_down_sync(0xFFFFFFFFu, vd, off);
    }
    if (lane == 0) { s[wid] = vs; d[wid] = vd; }
}

// ---------------------------------------------------------------------------
// Aggregation with online softmax. One warp per (node, head).
// ---------------------------------------------------------------------------
template <int ACT>
__global__ void agg_kernel(const float* __restrict__ h, const float* __restrict__ s,
                           const float* __restrict__ dts,
                           const float* __restrict__ bias,
                           float* __restrict__ out, int N, int H) {
    int wid = blockIdx.x * 8 + (threadIdx.x >> 5);
    int lane = threadIdx.x & 31;
    if (wid >= N * H) return;
    int n = wid / H;
    int hh = wid - n * H;
    int HC = H * 32;

    float sn = s[wid];
    float dn = dts[wid];
    float e0 = sn + dn;
    e0 = (e0 > 0.f) ? e0 : 0.2f * e0;

    float m = e0;
    float den = 1.f;
    float acc = h[(size_t)n * HC + hh * 32 + lane];

    int r0 = g_rowptr[n];
    int r1 = g_rowptr[n + 1];
    for (int j = r0; j < r1; ++j) {
        int src = g_col[j];
        float e = s[src * H + hh] + dn;
        e = (e > 0.f) ? e : 0.2f * e;
        float mn = fmaxf(m, e);
        float so = __expf(m - mn);
        float w  = __expf(e - mn);
        den = den * so + w;
        acc = acc * so + w * h[(size_t)src * HC + hh * 32 + lane];
        m = mn;
    }

    float o = acc / den + bias[hh * 32 + lane];
    if (ACT == 0) {
        out[(size_t)n * HC + hh * 32 + lane] = (o > 0.f) ? o : expm1f(o);
    } else {
        float mx = o;
        #pragma unroll
        for (int off = 16; off > 0; off >>= 1)
            mx = fmaxf(mx, __shfl_xor_sync(0xFFFFFFFFu, mx, off));
        float ex = __expf(o - mx);
        float sum = ex;
        #pragma unroll
        for (int off = 16; off > 0; off >>= 1)
            sum += __shfl_xor_sync(0xFFFFFFFFu, sum, off);
        out[(size_t)n * 32 + lane] = o - mx - logf(sum);
    }
}

// ---------------------------------------------------------------------------
// Launch
// ---------------------------------------------------------------------------
extern "C" void kernel_launch(void* const* d_in, const int* in_sizes, int n_in,
                              void* d_out, int out_size) {
    const float* x  = (const float*)d_in[0];
    const void*  ei = d_in[1];
    const float* W[4]    = {(const float*)d_in[2],  (const float*)d_in[6],
                            (const float*)d_in[10], (const float*)d_in[14]};
    const float* asrc[4] = {(const float*)d_in[3],  (const float*)d_in[7],
                            (const float*)d_in[11], (const float*)d_in[15]};
    const float* adst[4] = {(const float*)d_in[4],  (const float*)d_in[8],
                            (const float*)d_in[12], (const float*)d_in[16]};
    const float* bs[4]   = {(const float*)d_in[5],  (const float*)d_in[9],
                            (const float*)d_in[13], (const float*)d_in[17]};

    int N = in_sizes[0] / 256;
    int E = in_sizes[1] / 2;

    float *bufA, *bufB, *sb, *db;
    cudaGetSymbolAddress((void**)&bufA, g_bufA);
    cudaGetSymbolAddress((void**)&bufB, g_bufB);
    cudaGetSymbolAddress((void**)&sb,   g_s);
    cudaGetSymbolAddress((void**)&db,   g_d);

    // --- CSR build ---
    int nb = (N + 511) / 512;
    detect_dtype_kernel<<<1, 1>>>((const int*)ei, E);
    zero_deg_kernel<<<(N + 255) / 256, 256>>>(N);
    hist_kernel<<<(E + 255) / 256, 256>>>(ei, E);
    scan1_kernel<<<nb, 512>>>(N);
    scan2_kernel<<<1, 128>>>(nb, N);
    scan3_kernel<<<nb, 512>>>(N);
    scatter_kernel<<<(E + 255) / 256, 256>>>(ei, E);

    // --- 4 GAT layers ---
    const int Hs[4]  = {8, 4, 2, 1};
    const int Ks[4]  = {256, 256, 128, 64};
    const int HCs[4] = {256, 128, 64, 32};

    const float* in = x;
    for (int L = 0; L < 4; ++L) {
        int K = Ks[L], HC = HCs[L], H = Hs[L];
        if (L < 3) {
            dim3 g((N + 127) / 128, HC / 64);
            gemm_mma_kernel<64, 4, 2, 2><<<g, 256>>>(in, W[L], bufA, N, K, HC);
        } else {
            dim3 g((N + 127) / 128, 1);
            gemm_mma_kernel<32, 8, 1, 1><<<g, 256>>>(in, W[L], bufA, N, K, HC);
        }
        int warps = N * H;
        int blocks = (warps + 7) / 8;
        sd_kernel<<<blocks, 256>>>(bufA, asrc[L], adst[L], sb, db, N, H);
        if (L < 3) {
            agg_kernel<0><<<blocks, 256>>>(bufA, sb, db, bs[L], bufB, N, H);
            in = bufB;
        } else {
            agg_kernel<1><<<blocks, 256>>>(bufA, sb, db, bs[L], (float*)d_out, N, H);
        }
    }
}